// round 1
// baseline (speedup 1.0000x reference)
#include <cuda_runtime.h>
#include <cstdint>

// Problem constants
#define T_TOK 2048
#define H_DIM 2048
#define F_DIM 5632
#define E_NUM 8
#define K_TOP 2
#define F2    (2 * F_DIM)          // 11264
#define MAXROWS  5120              // 4096 pairs + per-expert 128-padding, rounded
#define MAXTILES 40                // MAXROWS / 128

// GEMM tiling
#define BM 128
#define BN 128
#define BK 32
#define PAD 36                     // SMEM row pitch (floats): conflict-free + 16B aligned rows (36*4=144)

// ---------------- device scratch (no allocations allowed) ----------------
__device__ float g_h  [(size_t)MAXROWS * F2];     // GEMM1 output (gate|up), ~231 MB
__device__ float g_act[(size_t)MAXROWS * F_DIM];  // silu(gate)*up, ~115 MB
__device__ int   g_tok[MAXROWS];
__device__ float g_wt [MAXROWS];
__device__ int   g_cnt[E_NUM];
__device__ int   g_off[E_NUM];
__device__ int   g_cursor[E_NUM];
__device__ int   g_tile_expert[MAXTILES];

// ---------------- small helpers ----------------
__device__ __forceinline__ uint32_t f2tf(float f) {
    uint32_t u;
    asm("cvt.rna.tf32.f32 %0, %1;" : "=r"(u) : "f"(f));
    return u;
}

__device__ __forceinline__ void mma8(float* d, const uint32_t* a, const uint32_t* b) {
    asm volatile(
        "mma.sync.aligned.m16n8k8.row.col.f32.tf32.tf32.f32 "
        "{%0,%1,%2,%3}, {%4,%5,%6,%7}, {%8,%9}, {%0,%1,%2,%3};\n"
        : "+f"(d[0]), "+f"(d[1]), "+f"(d[2]), "+f"(d[3])
        : "r"(a[0]), "r"(a[1]), "r"(a[2]), "r"(a[3]),
          "r"(b[0]), "r"(b[1]));
}

// ---------------- routing kernels ----------------
__global__ void k_init(float* __restrict__ out) {
    int tid  = blockIdx.x * blockDim.x + threadIdx.x;
    int nthr = gridDim.x * blockDim.x;
    for (int i = tid; i < T_TOK * H_DIM; i += nthr) out[i] = 0.0f;
    for (int i = tid; i < MAXROWS; i += nthr) { g_tok[i] = -1; g_wt[i] = 0.0f; }
    if (tid < E_NUM) g_cnt[tid] = 0;
}

__global__ void k_count(const int* __restrict__ sel) {
    int i = blockIdx.x * blockDim.x + threadIdx.x;
    if (i < T_TOK * K_TOP) atomicAdd(&g_cnt[sel[i]], 1);
}

__global__ void k_scan() {
    // single thread: tiny E=8 prefix with 128-row alignment + tile->expert map
    for (int t = 0; t < MAXTILES; ++t) g_tile_expert[t] = -1;
    int off = 0;
    for (int e = 0; e < E_NUM; ++e) {
        g_off[e]    = off;
        g_cursor[e] = off;
        int tiles = (g_cnt[e] + BM - 1) / BM;
        for (int j = 0; j < tiles; ++j) g_tile_expert[off / BM + j] = e;
        off += tiles * BM;
    }
}

__global__ void k_scatter(const int* __restrict__ sel, const float* __restrict__ rw) {
    int i = blockIdx.x * blockDim.x + threadIdx.x;
    if (i < T_TOK * K_TOP) {
        int e   = sel[i];
        int pos = atomicAdd(&g_cursor[e], 1);
        g_tok[pos] = i / K_TOP;
        g_wt[pos]  = rw[i];
    }
}

// ---------------- TF32 tiled GEMM: C = A * B^T ----------------
// MODE 1: A = gathered hidden_states [rows x H], B = W1[e] [2F x H] -> g_h
// MODE 2: A = g_act [rows x F],               B = W2[e] [H x F]    -> atomicAdd into out
template <int MODE>
__global__ __launch_bounds__(256, 2)
void k_gemm(const float* __restrict__ Ain,
            const float* __restrict__ W,
            float* __restrict__ out) {
    const int tile_n = blockIdx.x;
    const int tile_m = blockIdx.y;
    const int e = g_tile_expert[tile_m];
    if (e < 0) return;

    constexpr int KDIM  = (MODE == 1) ? H_DIM : F_DIM;
    constexpr int NCOLS = (MODE == 1) ? F2    : H_DIM;

    const float* Bbase = (MODE == 1)
        ? (W + (size_t)e * F2 * H_DIM)
        : (W + (size_t)e * H_DIM * F_DIM);

    __shared__ uint32_t As[BM][PAD];
    __shared__ uint32_t Bs[BN][PAD];

    const int tid  = threadIdx.x;
    const int lane = tid & 31;
    const int warp = tid >> 5;
    const int wm   = warp & 1;   // 2 warps along M
    const int wn   = warp >> 1;  // 4 warps along N
    const int rbase = wm * 64 + (lane >> 2);
    const int nbase = wn * 32 + (lane >> 2);

    float acc[4][4][4];
#pragma unroll
    for (int mt = 0; mt < 4; ++mt)
#pragma unroll
        for (int nt = 0; nt < 4; ++nt)
#pragma unroll
            for (int r = 0; r < 4; ++r) acc[mt][nt][r] = 0.0f;

    const int ld_sub = tid / 8;   // 0..31
    const int ld_k4  = tid % 8;   // 0..7 (float4 index within a 32-float row chunk)

    for (int kt = 0; kt < KDIM / BK; ++kt) {
        const int kbase = kt * BK;
        __syncthreads();   // previous compute done before overwrite

        // load A tile (128 x 32) and B tile (128 x 32), float4, tf32-convert at STS
#pragma unroll
        for (int i = 0; i < 4; ++i) {
            const int r = i * 32 + ld_sub;

            float4 va;
            if (MODE == 1) {
                const int tok = g_tok[tile_m * BM + r];
                if (tok >= 0)
                    va = *(const float4*)(Ain + (size_t)tok * H_DIM + kbase + ld_k4 * 4);
                else
                    va = make_float4(0.f, 0.f, 0.f, 0.f);
            } else {
                va = *(const float4*)(g_act + (size_t)(tile_m * BM + r) * F_DIM + kbase + ld_k4 * 4);
            }
            uint4 ua;
            ua.x = f2tf(va.x); ua.y = f2tf(va.y); ua.z = f2tf(va.z); ua.w = f2tf(va.w);
            *(uint4*)&As[r][ld_k4 * 4] = ua;

            const float4 vb = *(const float4*)(Bbase + (size_t)(tile_n * BN + r) * KDIM + kbase + ld_k4 * 4);
            uint4 ub;
            ub.x = f2tf(vb.x); ub.y = f2tf(vb.y); ub.z = f2tf(vb.z); ub.w = f2tf(vb.w);
            *(uint4*)&Bs[r][ld_k4 * 4] = ub;
        }
        __syncthreads();

        // compute: 4 k-steps of 8
#pragma unroll
        for (int ks = 0; ks < 4; ++ks) {
            const int kk = ks * 8 + (lane & 3);
            uint32_t af[4][4];
#pragma unroll
            for (int mt = 0; mt < 4; ++mt) {
                const int r = rbase + mt * 16;
                af[mt][0] = As[r    ][kk];
                af[mt][1] = As[r + 8][kk];
                af[mt][2] = As[r    ][kk + 4];
                af[mt][3] = As[r + 8][kk + 4];
            }
            uint32_t bf[4][2];
#pragma unroll
            for (int nt = 0; nt < 4; ++nt) {
                const int n = nbase + nt * 8;
                bf[nt][0] = Bs[n][kk];
                bf[nt][1] = Bs[n][kk + 4];
            }
#pragma unroll
            for (int mt = 0; mt < 4; ++mt)
#pragma unroll
                for (int nt = 0; nt < 4; ++nt)
                    mma8(acc[mt][nt], af[mt], bf[nt]);
        }
    }

    // epilogue
#pragma unroll
    for (int mt = 0; mt < 4; ++mt) {
        const int r0 = tile_m * BM + wm * 64 + mt * 16 + (lane >> 2);
#pragma unroll
        for (int nt = 0; nt < 4; ++nt) {
            const int c0 = tile_n * BN + wn * 32 + nt * 8 + (lane & 3) * 2;
            if (MODE == 1) {
                float* p0 = g_h + (size_t)r0 * F2 + c0;
                float* p1 = g_h + (size_t)(r0 + 8) * F2 + c0;
                p0[0] = acc[mt][nt][0]; p0[1] = acc[mt][nt][1];
                p1[0] = acc[mt][nt][2]; p1[1] = acc[mt][nt][3];
            } else {
                const int t0 = g_tok[r0];
                const int t1 = g_tok[r0 + 8];
                if (t0 >= 0) {
                    const float w = g_wt[r0];
                    atomicAdd(out + (size_t)t0 * H_DIM + c0,     w * acc[mt][nt][0]);
                    atomicAdd(out + (size_t)t0 * H_DIM + c0 + 1, w * acc[mt][nt][1]);
                }
                if (t1 >= 0) {
                    const float w = g_wt[r0 + 8];
                    atomicAdd(out + (size_t)t1 * H_DIM + c0,     w * acc[mt][nt][2]);
                    atomicAdd(out + (size_t)t1 * H_DIM + c0 + 1, w * acc[mt][nt][3]);
                }
            }
        }
    }
}

// ---------------- SiLU(gate) * up ----------------
__global__ void k_silu() {
    const int row = blockIdx.y;
    if (g_tile_expert[row >> 7] < 0) return;   // skip padding-only tiles
    const int col = blockIdx.x * blockDim.x + threadIdx.x;
    const float gate = g_h[(size_t)row * F2 + col];
    const float up   = g_h[(size_t)row * F2 + F_DIM + col];
    const float s    = gate / (1.0f + expf(-gate));
    g_act[(size_t)row * F_DIM + col] = s * up;
}

// ---------------- launch ----------------
extern "C" void kernel_launch(void* const* d_in, const int* in_sizes, int n_in,
                              void* d_out, int out_size) {
    const float* X   = (const float*)d_in[0];   // hidden_states [T, H]
    const float* rw  = (const float*)d_in[1];   // routing_weights [T, K]
    const int*   sel = (const int*)  d_in[2];   // selected_experts [T, K]
    const float* W1  = (const float*)d_in[3];   // [E, 2F, H]
    const float* W2  = (const float*)d_in[4];   // [E, H, F]
    float* out = (float*)d_out;                 // [T, H]

    k_init<<<256, 256>>>(out);
    k_count<<<(T_TOK * K_TOP + 255) / 256, 256>>>(sel);
    k_scan<<<1, 1>>>();
    k_scatter<<<(T_TOK * K_TOP + 255) / 256, 256>>>(sel, rw);

    dim3 g1(F2 / BN, MAXTILES);
    k_gemm<1><<<g1, 256>>>(X, W1, nullptr);

    dim3 gs(F_DIM / 256, MAXROWS);
    k_silu<<<gs, 256>>>();

    dim3 g2(H_DIM / BN, MAXTILES);
    k_gemm<2><<<g2, 256>>>(nullptr, W2, out);
}

// round 3
// speedup vs baseline: 1.1713x; 1.1713x over previous
#include <cuda_runtime.h>
#include <cstdint>

// ---------------- problem constants ----------------
#define T_TOK 2048
#define H_DIM 2048
#define F_DIM 5632
#define E_NUM 8
#define K_TOP 2
#define F2    (2 * F_DIM)

// ---------------- tiling ----------------
#define BM 128
#define BK 32
#define PADF 36                  // SMEM pitch in floats (144B, 16B-aligned, conflict-free frags)
#define MAXROWS  5120
#define MAXTILES 40              // MAXROWS / BM

// ---------------- device scratch ----------------
__device__ float g_xg [(size_t)MAXROWS * H_DIM];   // gathered, zero-padded tokens (40 MB)
__device__ float g_act[(size_t)MAXROWS * F_DIM];   // silu(gate)*up (110 MB)
__device__ int   g_tok[MAXROWS];
__device__ float g_wt [MAXROWS];
__device__ int   g_cnt[E_NUM];
__device__ int   g_cursor[E_NUM];
__device__ int   g_tile_expert[MAXTILES];

// ---------------- helpers ----------------
__device__ __forceinline__ uint32_t smem_u32(const void* p) {
    uint32_t a;
    asm("{ .reg .u64 t; cvta.to.shared.u64 t, %1; cvt.u32.u64 %0, t; }" : "=r"(a) : "l"(p));
    return a;
}
__device__ __forceinline__ uint32_t f2tf(float f) {
    uint32_t u;
    asm("cvt.rna.tf32.f32 %0, %1;" : "=r"(u) : "f"(f));
    return u;
}
__device__ __forceinline__ void cpa16(uint32_t dst, const void* src) {
    asm volatile("cp.async.cg.shared.global [%0], [%1], 16;" :: "r"(dst), "l"(src));
}
#define CPA_COMMIT() asm volatile("cp.async.commit_group;" ::: "memory")
#define CPA_WAIT0()  asm volatile("cp.async.wait_group 0;" ::: "memory")

__device__ __forceinline__ void mma8(float* d, const uint32_t* a, const uint32_t* b) {
    asm volatile(
        "mma.sync.aligned.m16n8k8.row.col.f32.tf32.tf32.f32 "
        "{%0,%1,%2,%3}, {%4,%5,%6,%7}, {%8,%9}, {%0,%1,%2,%3};\n"
        : "+f"(d[0]), "+f"(d[1]), "+f"(d[2]), "+f"(d[3])
        : "r"(a[0]), "r"(a[1]), "r"(a[2]), "r"(a[3]),
          "r"(b[0]), "r"(b[1]));
}

// ---------------- routing ----------------
__global__ void k_init(float* __restrict__ out) {
    int tid = blockIdx.x * blockDim.x + threadIdx.x;
    int nt  = gridDim.x * blockDim.x;
    for (int i = tid; i < T_TOK * H_DIM; i += nt) out[i] = 0.0f;
    for (int i = tid; i < MAXROWS; i += nt) { g_tok[i] = -1; g_wt[i] = 0.0f; }
    if (tid < E_NUM) g_cnt[tid] = 0;
}
__global__ void k_count(const int* __restrict__ sel) {
    int i = blockIdx.x * blockDim.x + threadIdx.x;
    if (i < T_TOK * K_TOP) atomicAdd(&g_cnt[sel[i]], 1);
}
__global__ void k_scan() {
    for (int t = 0; t < MAXTILES; ++t) g_tile_expert[t] = -1;
    int off = 0;
    for (int e = 0; e < E_NUM; ++e) {
        g_cursor[e] = off;
        int tiles = (g_cnt[e] + BM - 1) / BM;
        for (int j = 0; j < tiles; ++j) g_tile_expert[off / BM + j] = e;
        off += tiles * BM;
    }
}
__global__ void k_scatter(const int* __restrict__ sel, const float* __restrict__ rw) {
    int i = blockIdx.x * blockDim.x + threadIdx.x;
    if (i < T_TOK * K_TOP) {
        int e   = sel[i];
        int pos = atomicAdd(&g_cursor[e], 1);
        g_tok[pos] = i / K_TOP;
        g_wt[pos]  = rw[i];
    }
}
__global__ void k_gather(const float* __restrict__ X) {
    const int row = blockIdx.x;
    if (g_tile_expert[row >> 7] < 0) return;
    const int tok = g_tok[row];
    float4* dst = (float4*)(g_xg + (size_t)row * H_DIM);
    if (tok >= 0) {
        const float4* src = (const float4*)(X + (size_t)tok * H_DIM);
        for (int i = threadIdx.x; i < H_DIM / 4; i += blockDim.x) dst[i] = src[i];
    } else {
        for (int i = threadIdx.x; i < H_DIM / 4; i += blockDim.x)
            dst[i] = make_float4(0.f, 0.f, 0.f, 0.f);
    }
}

// ---------------- pipelined TF32 GEMM, cp.async double buffered ----------------
// MODE 1: A = g_xg [128 x H], B = 64 gate rows ‖ 64 up rows of W1[e]
//         -> epilogue fuses silu(gate)*up -> g_act (64 output cols per CTA)
// MODE 2: A = g_act [128 x F], B = 128 rows of W2[e] -> weighted atomicAdd -> out
template <int MODE>
__global__ void __launch_bounds__(256, 2)
k_gemm(const float* __restrict__ W, float* __restrict__ out) {
    constexpr int KD = (MODE == 1) ? H_DIM : F_DIM;
    constexpr int NC = KD / BK;                 // 64 or 176

    const int tile_n = blockIdx.x;
    const int tile_m = blockIdx.y;
    const int e = g_tile_expert[tile_m];
    if (e < 0) return;

    extern __shared__ float smem[];             // [2][2][128][PADF] : stage, A/B
    constexpr int TILEF  = BM * PADF;           // floats per (A or B) tile
    constexpr int STAGEF = 2 * TILEF;
    const uint32_t sb = smem_u32(smem);

    const int tid  = threadIdx.x;
    const int lane = tid & 31;
    const int warp = tid >> 5;
    const int wm   = warp & 1;                  // 2 warps along M
    const int wn   = warp >> 1;                 // 4 warps along N
    const int rbase = wm * 64 + (lane >> 2);
    const int nbase = wn * 32 + (lane >> 2);

    // per-thread cp.async source setup: 1024 16B-chunks per tile, 4 per thread
    const float* Abase = ((MODE == 1) ? g_xg : g_act) + (size_t)tile_m * BM * KD;
    const float* Bsrc[4];
    const float* Asrc[4];
    {
        const float* Bg;
        const float* Bu = nullptr;
        if (MODE == 1) {
            Bg = W + (size_t)e * F2 * H_DIM + (size_t)tile_n * 64 * H_DIM;   // gate rows
            Bu = Bg + (size_t)F_DIM * H_DIM;                                 // up rows
        } else {
            Bg = W + (size_t)e * H_DIM * F_DIM + (size_t)tile_n * BM * F_DIM;
        }
#pragma unroll
        for (int i = 0; i < 4; ++i) {
            const int idx = i * 256 + tid;
            const int row = idx >> 3;           // 0..127
            const int q   = idx & 7;            // 16B chunk in row
            Asrc[i] = Abase + (size_t)row * KD + q * 4;
            if (MODE == 1)
                Bsrc[i] = (row < 64 ? Bg + (size_t)row * KD : Bu + (size_t)(row - 64) * KD) + q * 4;
            else
                Bsrc[i] = Bg + (size_t)row * KD + q * 4;
        }
    }
    // matching SMEM dst offsets (bytes from stage base)
    uint32_t dstoff[4];
#pragma unroll
    for (int i = 0; i < 4; ++i) {
        const int idx = i * 256 + tid;
        dstoff[i] = (uint32_t)((idx >> 3) * PADF + (idx & 7) * 4) * 4;
    }

    float acc[4][4][4];
#pragma unroll
    for (int mt = 0; mt < 4; ++mt)
#pragma unroll
        for (int nt = 0; nt < 4; ++nt)
#pragma unroll
            for (int r = 0; r < 4; ++r) acc[mt][nt][r] = 0.0f;

    // prologue: stage 0 <- chunk 0
#pragma unroll
    for (int i = 0; i < 4; ++i) {
        cpa16(sb + dstoff[i], Asrc[i]);
        cpa16(sb + (uint32_t)TILEF * 4 + dstoff[i], Bsrc[i]);
    }
    CPA_COMMIT();

#pragma unroll 1
    for (int c = 0; c < NC; ++c) {
        const int s = c & 1;
        CPA_WAIT0();
        __syncthreads();

        if (c + 1 < NC) {
            const int s1 = (c + 1) & 1;
            const uint32_t sbase = sb + (uint32_t)(s1 * STAGEF) * 4;
            const int koff = (c + 1) * BK;
#pragma unroll
            for (int i = 0; i < 4; ++i) {
                cpa16(sbase + dstoff[i], Asrc[i] + koff);
                cpa16(sbase + (uint32_t)TILEF * 4 + dstoff[i], Bsrc[i] + koff);
            }
            CPA_COMMIT();
        }

        const float* As = smem + s * STAGEF;
        const float* Bs = As + TILEF;
#pragma unroll
        for (int ks = 0; ks < 4; ++ks) {
            const int kk = ks * 8 + (lane & 3);
            uint32_t af[4][4];
#pragma unroll
            for (int mt = 0; mt < 4; ++mt) {
                const int r = rbase + mt * 16;
                af[mt][0] = f2tf(As[r * PADF + kk]);
                af[mt][1] = f2tf(As[(r + 8) * PADF + kk]);
                af[mt][2] = f2tf(As[r * PADF + kk + 4]);
                af[mt][3] = f2tf(As[(r + 8) * PADF + kk + 4]);
            }
            uint32_t bf[4][2];
#pragma unroll
            for (int nt = 0; nt < 4; ++nt) {
                const int n = nbase + nt * 8;
                bf[nt][0] = f2tf(Bs[n * PADF + kk]);
                bf[nt][1] = f2tf(Bs[n * PADF + kk + 4]);
            }
#pragma unroll
            for (int mt = 0; mt < 4; ++mt)
#pragma unroll
                for (int nt = 0; nt < 4; ++nt)
                    mma8(acc[mt][nt], af[mt], bf[nt]);
        }
    }

    // ---------------- epilogue ----------------
    if (MODE == 1) {
        // exchange gate fragments via SMEM, combine with up, write g_act
        constexpr int XP = 65;                  // exchange pitch (floats)
        float* xg = smem;                       // 128 x 65 floats (33 KB, fits stage mem)
        __syncthreads();
        if (wn < 2) {                           // gate warps: cols wn*32..
#pragma unroll
            for (int mt = 0; mt < 4; ++mt) {
                const int r0 = wm * 64 + mt * 16 + (lane >> 2);
#pragma unroll
                for (int nt = 0; nt < 4; ++nt) {
                    const int c0 = wn * 32 + nt * 8 + (lane & 3) * 2;
                    xg[r0 * XP + c0]           = acc[mt][nt][0];
                    xg[r0 * XP + c0 + 1]       = acc[mt][nt][1];
                    xg[(r0 + 8) * XP + c0]     = acc[mt][nt][2];
                    xg[(r0 + 8) * XP + c0 + 1] = acc[mt][nt][3];
                }
            }
        }
        __syncthreads();
        if (wn >= 2) {                          // up warps: same cols (wn-2)*32..
#pragma unroll
            for (int mt = 0; mt < 4; ++mt) {
                const int rl = wm * 64 + mt * 16 + (lane >> 2);
                const int grow0 = tile_m * BM + rl;
#pragma unroll
                for (int nt = 0; nt < 4; ++nt) {
                    const int c0 = (wn - 2) * 32 + nt * 8 + (lane & 3) * 2;
                    float g0 = xg[rl * XP + c0];
                    float g1 = xg[rl * XP + c0 + 1];
                    float g2 = xg[(rl + 8) * XP + c0];
                    float g3 = xg[(rl + 8) * XP + c0 + 1];
                    float2 o0, o1;
                    o0.x = acc[mt][nt][0] * g0 / (1.0f + expf(-g0));
                    o0.y = acc[mt][nt][1] * g1 / (1.0f + expf(-g1));
                    o1.x = acc[mt][nt][2] * g2 / (1.0f + expf(-g2));
                    o1.y = acc[mt][nt][3] * g3 / (1.0f + expf(-g3));
                    *(float2*)(g_act + (size_t)grow0 * F_DIM + tile_n * 64 + c0)       = o0;
                    *(float2*)(g_act + (size_t)(grow0 + 8) * F_DIM + tile_n * 64 + c0) = o1;
                }
            }
        }
    } else {
#pragma unroll
        for (int mt = 0; mt < 4; ++mt) {
            const int r0 = tile_m * BM + wm * 64 + mt * 16 + (lane >> 2);
            const int t0 = g_tok[r0];
            const int t1 = g_tok[r0 + 8];
            const float w0 = g_wt[r0];
            const float w1 = g_wt[r0 + 8];
#pragma unroll
            for (int nt = 0; nt < 4; ++nt) {
                const int c0 = tile_n * BM + wn * 32 + nt * 8 + (lane & 3) * 2;
                if (t0 >= 0) {
                    atomicAdd(out + (size_t)t0 * H_DIM + c0,     w0 * acc[mt][nt][0]);
                    atomicAdd(out + (size_t)t0 * H_DIM + c0 + 1, w0 * acc[mt][nt][1]);
                }
                if (t1 >= 0) {
                    atomicAdd(out + (size_t)t1 * H_DIM + c0,     w1 * acc[mt][nt][2]);
                    atomicAdd(out + (size_t)t1 * H_DIM + c0 + 1, w1 * acc[mt][nt][3]);
                }
            }
        }
    }
}

// ---------------- launch ----------------
extern "C" void kernel_launch(void* const* d_in, const int* in_sizes, int n_in,
                              void* d_out, int out_size) {
    const float* X   = (const float*)d_in[0];
    const float* rw  = (const float*)d_in[1];
    const int*   sel = (const int*)  d_in[2];
    const float* W1  = (const float*)d_in[3];
    const float* W2  = (const float*)d_in[4];
    float* out = (float*)d_out;

    constexpr int SMEM = 2 * 2 * BM * PADF * 4;   // 73728 bytes
    static int cfg = 0;
    if (!cfg) {
        cudaFuncSetAttribute(k_gemm<1>, cudaFuncAttributeMaxDynamicSharedMemorySize, SMEM);
        cudaFuncSetAttribute(k_gemm<2>, cudaFuncAttributeMaxDynamicSharedMemorySize, SMEM);
        cfg = 1;
    }

    k_init<<<256, 256>>>(out);
    k_count<<<(T_TOK * K_TOP + 255) / 256, 256>>>(sel);
    k_scan<<<1, 1>>>();
    k_scatter<<<(T_TOK * K_TOP + 255) / 256, 256>>>(sel, rw);
    k_gather<<<MAXROWS, 256>>>(X);

    dim3 g1(F_DIM / 64, MAXTILES);    // 88 x 40
    k_gemm<1><<<g1, 256, SMEM>>>(W1, nullptr);

    dim3 g2(H_DIM / BM, MAXTILES);    // 16 x 40
    k_gemm<2><<<g2, 256, SMEM>>>(W2, out);
}

// round 5
// speedup vs baseline: 2.0290x; 1.7323x over previous
#include <cuda_runtime.h>
#include <cuda_fp16.h>
#include <cstdint>

// ---------------- problem constants ----------------
#define T_TOK 2048
#define H_DIM 2048
#define F_DIM 5632
#define E_NUM 8
#define K_TOP 2
#define F2    (2 * F_DIM)

// ---------------- tiling ----------------
#define BM 128
#define BK 64                     // K halves per pipeline chunk (128B/row)
#define PITCH 72                  // SMEM row pitch in halves (144B: 16B-aligned, conflict-free)
#define TILE_B (BM * PITCH * 2)   // bytes per A or B tile = 18432
#define STAGE_B (2 * TILE_B)      // 36864
#define MAXROWS  5120
#define MAXTILES 40

// ---------------- device scratch ----------------
__device__ __half g_W1h[(size_t)E_NUM * F2 * H_DIM];      // 369 MB
__device__ __half g_W2h[(size_t)E_NUM * H_DIM * F_DIM];   // 185 MB
__device__ __half g_xg [(size_t)MAXROWS * H_DIM];         // 20 MB
__device__ __half g_act[(size_t)MAXROWS * F_DIM];         // 58 MB
__device__ int   g_tok[MAXROWS];
__device__ float g_wt [MAXROWS];
__device__ int   g_cnt[E_NUM];
__device__ int   g_cursor[E_NUM];
__device__ int   g_tile_expert[MAXTILES];

// ---------------- helpers ----------------
__device__ __forceinline__ uint32_t smem_u32(const void* p) {
    uint32_t a;
    asm("{ .reg .u64 t; cvta.to.shared.u64 t, %1; cvt.u32.u64 %0, t; }" : "=r"(a) : "l"(p));
    return a;
}
__device__ __forceinline__ void cpa16(uint32_t dst, const void* src) {
    asm volatile("cp.async.cg.shared.global [%0], [%1], 16;" :: "r"(dst), "l"(src));
}
#define CPA_COMMIT() asm volatile("cp.async.commit_group;" ::: "memory")
#define CPA_WAIT0()  asm volatile("cp.async.wait_group 0;" ::: "memory")

__device__ __forceinline__ void ldm4(uint32_t* r, uint32_t addr) {
    asm volatile("ldmatrix.sync.aligned.m8n8.x4.shared.b16 {%0,%1,%2,%3}, [%4];"
                 : "=r"(r[0]), "=r"(r[1]), "=r"(r[2]), "=r"(r[3]) : "r"(addr));
}
__device__ __forceinline__ uint32_t lds32(uint32_t addr) {
    uint32_t v;
    asm volatile("ld.shared.b32 %0, [%1];" : "=r"(v) : "r"(addr));
    return v;
}
__device__ __forceinline__ void mma16816(float* d, const uint32_t* a, const uint32_t* b) {
    asm volatile(
        "mma.sync.aligned.m16n8k16.row.col.f32.f16.f16.f32 "
        "{%0,%1,%2,%3}, {%4,%5,%6,%7}, {%8,%9}, {%0,%1,%2,%3};\n"
        : "+f"(d[0]), "+f"(d[1]), "+f"(d[2]), "+f"(d[3])
        : "r"(a[0]), "r"(a[1]), "r"(a[2]), "r"(a[3]),
          "r"(b[0]), "r"(b[1]));
}
__device__ __forceinline__ uint32_t pack_h2(float a, float b) {
    __half2 h = __floats2half2_rn(a, b);
    return *(uint32_t*)&h;
}

// ---------------- routing ----------------
__global__ void k_init(float* __restrict__ out) {
    int tid = blockIdx.x * blockDim.x + threadIdx.x;
    int nt  = gridDim.x * blockDim.x;
    for (int i = tid; i < T_TOK * H_DIM; i += nt) out[i] = 0.0f;
    for (int i = tid; i < MAXROWS; i += nt) { g_tok[i] = -1; g_wt[i] = 0.0f; }
    if (tid < E_NUM) g_cnt[tid] = 0;
}
__global__ void k_count(const int* __restrict__ sel) {
    int i = blockIdx.x * blockDim.x + threadIdx.x;
    if (i < T_TOK * K_TOP) atomicAdd(&g_cnt[sel[i]], 1);
}
__global__ void k_scan() {
    for (int t = 0; t < MAXTILES; ++t) g_tile_expert[t] = -1;
    int off = 0;
    for (int e = 0; e < E_NUM; ++e) {
        g_cursor[e] = off;
        int tiles = (g_cnt[e] + BM - 1) / BM;
        for (int j = 0; j < tiles; ++j) g_tile_expert[off / BM + j] = e;
        off += tiles * BM;
    }
}
__global__ void k_scatter(const int* __restrict__ sel, const float* __restrict__ rw) {
    int i = blockIdx.x * blockDim.x + threadIdx.x;
    if (i < T_TOK * K_TOP) {
        int e   = sel[i];
        int pos = atomicAdd(&g_cursor[e], 1);
        g_tok[pos] = i / K_TOP;
        g_wt[pos]  = rw[i];
    }
}
// gather tokens into g_xg as fp16 (rn conversion here, not in GEMM)
__global__ void k_gather(const float* __restrict__ X) {
    const int row = blockIdx.x;
    if (g_tile_expert[row >> 7] < 0) return;
    const int tok = g_tok[row];
    uint2* dst = (uint2*)(g_xg + (size_t)row * H_DIM);
    if (tok >= 0) {
        const float4* src = (const float4*)(X + (size_t)tok * H_DIM);
        for (int i = threadIdx.x; i < H_DIM / 4; i += blockDim.x) {
            float4 v = src[i];
            uint2 o;
            o.x = pack_h2(v.x, v.y);
            o.y = pack_h2(v.z, v.w);
            dst[i] = o;
        }
    } else {
        for (int i = threadIdx.x; i < H_DIM / 4; i += blockDim.x)
            dst[i] = make_uint2(0u, 0u);
    }
}
// streaming fp32 -> fp16 weight conversion
__global__ void k_cvt(const float* __restrict__ src, __half* __restrict__ dst, size_t n4) {
    size_t i = (size_t)blockIdx.x * blockDim.x + threadIdx.x;
    size_t stride = (size_t)gridDim.x * blockDim.x;
    for (; i < n4; i += stride) {
        float4 v = ((const float4*)src)[i];
        uint2 o;
        o.x = pack_h2(v.x, v.y);
        o.y = pack_h2(v.z, v.w);
        ((uint2*)dst)[i] = o;
    }
}

// ---------------- fp16 tensor GEMM, cp.async double buffered ----------------
// MODE 1: A = g_xg [128 x H], B = 64 gate rows ‖ 64 up rows of W1h[e]
//         -> epilogue fuses silu(gate)*up -> g_act (fp16, 64 cols per CTA)
// MODE 2: A = g_act [128 x F], B = 128 rows of W2h[e] -> weighted atomicAdd -> out
template <int MODE>
__global__ void __launch_bounds__(256, 2)
k_gemm(const __half* __restrict__ Wh, float* __restrict__ out) {
    constexpr int KD = (MODE == 1) ? H_DIM : F_DIM;
    constexpr int NC = KD / BK;                // 32 or 88

    const int tile_n = blockIdx.x;
    const int tile_m = blockIdx.y;
    const int e = g_tile_expert[tile_m];
    if (e < 0) return;

    extern __shared__ char smem[];
    const uint32_t sb = smem_u32(smem);

    const int tid  = threadIdx.x;
    const int lane = tid & 31;
    const int warp = tid >> 5;
    const int wm   = warp & 1;                 // 2 warps along M
    const int wn   = warp >> 1;                // 4 warps along N

    // cp.async sources: 1024 16B chunks per tile, 4 per thread each for A and B
    const __half* Abase = ((MODE == 1) ? g_xg : g_act) + (size_t)tile_m * BM * KD;
    const __half* Asrc[4];
    const __half* Bsrc[4];
    uint32_t doff[4];
    {
        const __half* Bg;
        const __half* Bu = nullptr;
        if (MODE == 1) {
            Bg = Wh + (size_t)e * F2 * H_DIM + (size_t)tile_n * 64 * H_DIM;  // gate rows
            Bu = Bg + (size_t)F_DIM * H_DIM;                                 // up rows
        } else {
            Bg = Wh + (size_t)e * H_DIM * F_DIM + (size_t)tile_n * BM * F_DIM;
        }
#pragma unroll
        for (int i = 0; i < 4; ++i) {
            const int idx = i * 256 + tid;
            const int row = idx >> 3;          // 0..127
            const int q   = idx & 7;           // 16B chunk in 128B row-chunk
            Asrc[i] = Abase + (size_t)row * KD + q * 8;
            if (MODE == 1)
                Bsrc[i] = (row < 64 ? Bg + (size_t)row * KD : Bu + (size_t)(row - 64) * KD) + q * 8;
            else
                Bsrc[i] = Bg + (size_t)row * KD + q * 8;
            doff[i] = (uint32_t)(row * (PITCH * 2) + q * 16);
        }
    }

    float acc[4][4][4];
#pragma unroll
    for (int mt = 0; mt < 4; ++mt)
#pragma unroll
        for (int nt = 0; nt < 4; ++nt)
#pragma unroll
            for (int r = 0; r < 4; ++r) acc[mt][nt][r] = 0.0f;

    // ldmatrix per-lane base (bytes within A tile):
    // lanes 0-7: rows 0-7 k-lo | 8-15: rows 8-15 k-lo | 16-23: rows 0-7 k-hi | 24-31: rows 8-15 k-hi
    const uint32_t lmoff = (uint32_t)((wm * 64 + (lane & 7) + ((lane >> 3) & 1) * 8) * (PITCH * 2)
                                      + (lane >> 4) * 16);
    // B fragment LDS.32 base (bytes within B tile): n = wn*32 + (lane>>2), k-pair at (lane&3)*2 halves
    const uint32_t lboff = (uint32_t)((wn * 32 + (lane >> 2)) * (PITCH * 2) + (lane & 3) * 4);

    // prologue: stage 0 <- chunk 0
#pragma unroll
    for (int i = 0; i < 4; ++i) {
        cpa16(sb + doff[i], Asrc[i]);
        cpa16(sb + TILE_B + doff[i], Bsrc[i]);
    }
    CPA_COMMIT();

#pragma unroll 1
    for (int c = 0; c < NC; ++c) {
        const int s = c & 1;
        CPA_WAIT0();
        __syncthreads();

        if (c + 1 < NC) {
            const uint32_t base = sb + ((c + 1) & 1) * STAGE_B;
            const int koff = (c + 1) * BK;
#pragma unroll
            for (int i = 0; i < 4; ++i) {
                cpa16(base + doff[i], Asrc[i] + koff);
                cpa16(base + TILE_B + doff[i], Bsrc[i] + koff);
            }
            CPA_COMMIT();
        }

        const uint32_t As = sb + s * STAGE_B;
        const uint32_t Bs = As + TILE_B;
#pragma unroll
        for (int ks = 0; ks < 4; ++ks) {           // 4 x K=16
            uint32_t a[4][4];
#pragma unroll
            for (int mt = 0; mt < 4; ++mt)
                ldm4(a[mt], As + lmoff + mt * 16 * (PITCH * 2) + ks * 32);
            uint32_t b[4][2];
#pragma unroll
            for (int nt = 0; nt < 4; ++nt) {
                const uint32_t ad = Bs + lboff + nt * 8 * (PITCH * 2) + ks * 32;
                b[nt][0] = lds32(ad);
                b[nt][1] = lds32(ad + 16);
            }
#pragma unroll
            for (int mt = 0; mt < 4; ++mt)
#pragma unroll
                for (int nt = 0; nt < 4; ++nt)
                    mma16816(acc[mt][nt], a[mt], b[nt]);
        }
    }

    // ---------------- epilogue ----------------
    if (MODE == 1) {
        // exchange gate via fp32 SMEM, combine with up, store fp16 to g_act
        constexpr int XP = 65;
        float* xg = (float*)smem;               // 128 x 65 floats = 33 KB
        __syncthreads();
        if (wn < 2) {                           // gate warps: cols wn*32..
#pragma unroll
            for (int mt = 0; mt < 4; ++mt) {
                const int r0 = wm * 64 + mt * 16 + (lane >> 2);
#pragma unroll
                for (int nt = 0; nt < 4; ++nt) {
                    const int c0 = wn * 32 + nt * 8 + (lane & 3) * 2;
                    xg[r0 * XP + c0]           = acc[mt][nt][0];
                    xg[r0 * XP + c0 + 1]       = acc[mt][nt][1];
                    xg[(r0 + 8) * XP + c0]     = acc[mt][nt][2];
                    xg[(r0 + 8) * XP + c0 + 1] = acc[mt][nt][3];
                }
            }
        }
        __syncthreads();
        if (wn >= 2) {                          // up warps: same cols (wn-2)*32..
#pragma unroll
            for (int mt = 0; mt < 4; ++mt) {
                const int rl = wm * 64 + mt * 16 + (lane >> 2);
                const int grow0 = tile_m * BM + rl;
#pragma unroll
                for (int nt = 0; nt < 4; ++nt) {
                    const int c0 = (wn - 2) * 32 + nt * 8 + (lane & 3) * 2;
                    float g0 = xg[rl * XP + c0];
                    float g1 = xg[rl * XP + c0 + 1];
                    float g2 = xg[(rl + 8) * XP + c0];
                    float g3 = xg[(rl + 8) * XP + c0 + 1];
                    float o0 = acc[mt][nt][0] * g0 / (1.0f + expf(-g0));
                    float o1 = acc[mt][nt][1] * g1 / (1.0f + expf(-g1));
                    float o2 = acc[mt][nt][2] * g2 / (1.0f + expf(-g2));
                    float o3 = acc[mt][nt][3] * g3 / (1.0f + expf(-g3));
                    *(uint32_t*)(g_act + (size_t)grow0 * F_DIM + tile_n * 64 + c0)       = pack_h2(o0, o1);
                    *(uint32_t*)(g_act + (size_t)(grow0 + 8) * F_DIM + tile_n * 64 + c0) = pack_h2(o2, o3);
                }
            }
        }
    } else {
#pragma unroll
        for (int mt = 0; mt < 4; ++mt) {
            const int r0 = tile_m * BM + wm * 64 + mt * 16 + (lane >> 2);
            const int t0 = g_tok[r0];
            const int t1 = g_tok[r0 + 8];
            const float w0 = g_wt[r0];
            const float w1 = g_wt[r0 + 8];
#pragma unroll
            for (int nt = 0; nt < 4; ++nt) {
                const int c0 = tile_n * BM + wn * 32 + nt * 8 + (lane & 3) * 2;
                if (t0 >= 0) {
                    atomicAdd(out + (size_t)t0 * H_DIM + c0,     w0 * acc[mt][nt][0]);
                    atomicAdd(out + (size_t)t0 * H_DIM + c0 + 1, w0 * acc[mt][nt][1]);
                }
                if (t1 >= 0) {
                    atomicAdd(out + (size_t)t1 * H_DIM + c0,     w1 * acc[mt][nt][2]);
                    atomicAdd(out + (size_t)t1 * H_DIM + c0 + 1, w1 * acc[mt][nt][3]);
                }
            }
        }
    }
}

// ---------------- launch ----------------
extern "C" void kernel_launch(void* const* d_in, const int* in_sizes, int n_in,
                              void* d_out, int out_size) {
    const float* X   = (const float*)d_in[0];
    const float* rw  = (const float*)d_in[1];
    const int*   sel = (const int*)  d_in[2];
    const float* W1  = (const float*)d_in[3];
    const float* W2  = (const float*)d_in[4];
    float* out = (float*)d_out;

    constexpr int SMEM = 2 * STAGE_B;          // 73728 bytes
    static int cfg = 0;
    static __half* w1h = nullptr;
    static __half* w2h = nullptr;
    if (!cfg) {
        cudaFuncSetAttribute(k_gemm<1>, cudaFuncAttributeMaxDynamicSharedMemorySize, SMEM);
        cudaFuncSetAttribute(k_gemm<2>, cudaFuncAttributeMaxDynamicSharedMemorySize, SMEM);
        cudaGetSymbolAddress((void**)&w1h, g_W1h);
        cudaGetSymbolAddress((void**)&w2h, g_W2h);
        cfg = 1;
    }

    k_init<<<256, 256>>>(out);
    k_count<<<(T_TOK * K_TOP + 255) / 256, 256>>>(sel);
    k_scan<<<1, 1>>>();
    k_scatter<<<(T_TOK * K_TOP + 255) / 256, 256>>>(sel, rw);
    k_gather<<<MAXROWS, 256>>>(X);

    k_cvt<<<4096, 256>>>(W1, w1h, (size_t)E_NUM * F2 * H_DIM / 4);
    k_cvt<<<4096, 256>>>(W2, w2h, (size_t)E_NUM * H_DIM * F_DIM / 4);

    dim3 g1(F_DIM / 64, MAXTILES);    // 88 x 40
    k_gemm<1><<<g1, 256, SMEM>>>(w1h, nullptr);

    dim3 g2(H_DIM / BM, MAXTILES);    // 16 x 40
    k_gemm<2><<<g2, 256, SMEM>>>(w2h, out);
}

// round 6
// speedup vs baseline: 2.2072x; 1.0878x over previous
#include <cuda_runtime.h>
#include <cuda_fp16.h>
#include <cstdint>

// ---------------- problem constants ----------------
#define T_TOK 2048
#define H_DIM 2048
#define F_DIM 5632
#define E_NUM 8
#define K_TOP 2
#define F2    (2 * F_DIM)

// ---------------- tiling ----------------
#define BM 128
#define BK 64                     // K halves per pipeline chunk (128B/row)
#define PITCH 72                  // SMEM row pitch in halves (144B)
#define TILE_B (BM * PITCH * 2)   // 18432 bytes per A or B tile
#define STAGE_B (2 * TILE_B)      // 36864
#define NSTAGE 3
#define MAXROWS  5120
#define MAXTILES 40

// ---------------- device scratch ----------------
__device__ __half g_W1h[(size_t)E_NUM * F2 * H_DIM];
__device__ __half g_W2h[(size_t)E_NUM * H_DIM * F_DIM];
__device__ __half g_xg [(size_t)MAXROWS * H_DIM];
__device__ __half g_act[(size_t)MAXROWS * F_DIM];
__device__ int   g_tok[MAXROWS];
__device__ float g_wt [MAXROWS];
__device__ int   g_cnt[E_NUM];
__device__ int   g_cursor[E_NUM];
__device__ int   g_tile_expert[MAXTILES];

// ---------------- helpers ----------------
__device__ __forceinline__ uint32_t smem_u32(const void* p) {
    uint32_t a;
    asm("{ .reg .u64 t; cvta.to.shared.u64 t, %1; cvt.u32.u64 %0, t; }" : "=r"(a) : "l"(p));
    return a;
}
__device__ __forceinline__ void cpa16(uint32_t dst, const void* src) {
    asm volatile("cp.async.cg.shared.global [%0], [%1], 16;" :: "r"(dst), "l"(src));
}
#define CPA_COMMIT() asm volatile("cp.async.commit_group;" ::: "memory")
#define CPA_WAIT0()  asm volatile("cp.async.wait_group 0;" ::: "memory")
#define CPA_WAIT1()  asm volatile("cp.async.wait_group 1;" ::: "memory")

__device__ __forceinline__ void ldm4(uint32_t* r, uint32_t addr) {
    asm volatile("ldmatrix.sync.aligned.m8n8.x4.shared.b16 {%0,%1,%2,%3}, [%4];"
                 : "=r"(r[0]), "=r"(r[1]), "=r"(r[2]), "=r"(r[3]) : "r"(addr));
}
__device__ __forceinline__ void mma16816(float* d, const uint32_t* a, const uint32_t* b) {
    asm volatile(
        "mma.sync.aligned.m16n8k16.row.col.f32.f16.f16.f32 "
        "{%0,%1,%2,%3}, {%4,%5,%6,%7}, {%8,%9}, {%0,%1,%2,%3};\n"
        : "+f"(d[0]), "+f"(d[1]), "+f"(d[2]), "+f"(d[3])
        : "r"(a[0]), "r"(a[1]), "r"(a[2]), "r"(a[3]),
          "r"(b[0]), "r"(b[1]));
}
__device__ __forceinline__ uint32_t pack_h2(float a, float b) {
    __half2 h = __floats2half2_rn(a, b);
    return *(uint32_t*)&h;
}

// ---------------- routing ----------------
__global__ void k_init(float* __restrict__ out) {
    int tid = blockIdx.x * blockDim.x + threadIdx.x;
    int nt  = gridDim.x * blockDim.x;
    for (int i = tid; i < T_TOK * H_DIM; i += nt) out[i] = 0.0f;
    for (int i = tid; i < MAXROWS; i += nt) { g_tok[i] = -1; g_wt[i] = 0.0f; }
    if (tid < E_NUM) g_cnt[tid] = 0;
}
__global__ void k_count(const int* __restrict__ sel) {
    int i = blockIdx.x * blockDim.x + threadIdx.x;
    if (i < T_TOK * K_TOP) atomicAdd(&g_cnt[sel[i]], 1);
}
__global__ void k_scan() {
    for (int t = 0; t < MAXTILES; ++t) g_tile_expert[t] = -1;
    int off = 0;
    for (int e = 0; e < E_NUM; ++e) {
        g_cursor[e] = off;
        int tiles = (g_cnt[e] + BM - 1) / BM;
        for (int j = 0; j < tiles; ++j) g_tile_expert[off / BM + j] = e;
        off += tiles * BM;
    }
}
__global__ void k_scatter(const int* __restrict__ sel, const float* __restrict__ rw) {
    int i = blockIdx.x * blockDim.x + threadIdx.x;
    if (i < T_TOK * K_TOP) {
        int e   = sel[i];
        int pos = atomicAdd(&g_cursor[e], 1);
        g_tok[pos] = i / K_TOP;
        g_wt[pos]  = rw[i];
    }
}
__global__ void k_gather(const float* __restrict__ X) {
    const int row = blockIdx.x;
    if (g_tile_expert[row >> 7] < 0) return;
    const int tok = g_tok[row];
    uint2* dst = (uint2*)(g_xg + (size_t)row * H_DIM);
    if (tok >= 0) {
        const float4* src = (const float4*)(X + (size_t)tok * H_DIM);
        for (int i = threadIdx.x; i < H_DIM / 4; i += blockDim.x) {
            float4 v = src[i];
            dst[i] = make_uint2(pack_h2(v.x, v.y), pack_h2(v.z, v.w));
        }
    } else {
        for (int i = threadIdx.x; i < H_DIM / 4; i += blockDim.x)
            dst[i] = make_uint2(0u, 0u);
    }
}
__global__ void k_cvt(const float* __restrict__ src, __half* __restrict__ dst, size_t n4) {
    size_t i = (size_t)blockIdx.x * blockDim.x + threadIdx.x;
    size_t stride = (size_t)gridDim.x * blockDim.x;
    for (; i < n4; i += stride) {
        float4 v = ((const float4*)src)[i];
        ((uint2*)dst)[i] = make_uint2(pack_h2(v.x, v.y), pack_h2(v.z, v.w));
    }
}

// ---------------- fp16 tensor GEMM, 3-stage cp.async ----------------
// MODE 1: A = g_xg [128 x H], B = 64 gate ‖ 64 up rows of W1h[e] -> silu fuse -> g_act
// MODE 2: A = g_act [128 x F], B = 128 rows of W2h[e] -> weighted atomicAdd -> out
template <int MODE>
__global__ void __launch_bounds__(256, 2)
k_gemm(const __half* __restrict__ Wh, float* __restrict__ out, int elo, int ehi) {
    constexpr int KD = (MODE == 1) ? H_DIM : F_DIM;
    constexpr int NC = KD / BK;                // 32 or 88

    const int tile_n = blockIdx.x;
    const int tile_m = blockIdx.y;
    const int e = g_tile_expert[tile_m];
    if (e < elo || e >= ehi) return;

    extern __shared__ char smem[];
    const uint32_t sb = smem_u32(smem);

    const int tid  = threadIdx.x;
    const int lane = tid & 31;
    const int warp = tid >> 5;
    const int wm   = warp & 1;
    const int wn   = warp >> 1;

    const __half* Abase = ((MODE == 1) ? g_xg : g_act) + (size_t)tile_m * BM * KD;
    const __half* Asrc[4];
    const __half* Bsrc[4];
    uint32_t doff[4];
    {
        const __half* Bg;
        const __half* Bu = nullptr;
        if (MODE == 1) {
            Bg = Wh + (size_t)e * F2 * H_DIM + (size_t)tile_n * 64 * H_DIM;
            Bu = Bg + (size_t)F_DIM * H_DIM;
        } else {
            Bg = Wh + (size_t)e * H_DIM * F_DIM + (size_t)tile_n * BM * F_DIM;
        }
#pragma unroll
        for (int i = 0; i < 4; ++i) {
            const int idx = i * 256 + tid;
            const int row = idx >> 3;
            const int q   = idx & 7;
            Asrc[i] = Abase + (size_t)row * KD + q * 8;
            if (MODE == 1)
                Bsrc[i] = (row < 64 ? Bg + (size_t)row * KD : Bu + (size_t)(row - 64) * KD) + q * 8;
            else
                Bsrc[i] = Bg + (size_t)row * KD + q * 8;
            doff[i] = (uint32_t)(row * (PITCH * 2) + q * 16);
        }
    }

    float acc[4][4][4];
#pragma unroll
    for (int mt = 0; mt < 4; ++mt)
#pragma unroll
        for (int nt = 0; nt < 4; ++nt)
#pragma unroll
            for (int r = 0; r < 4; ++r) acc[mt][nt][r] = 0.0f;

    // A ldmatrix lane base
    const uint32_t lmoff = (uint32_t)((wm * 64 + (lane & 7) + ((lane >> 3) & 1) * 8) * (PITCH * 2)
                                      + (lane >> 4) * 16);
    // B ldmatrix lane base: matrix m = lane>>3 -> (n-block m>>1, k-half m&1)
    const uint32_t lbofr = (uint32_t)((wn * 32 + ((lane >> 4) & 1) * 8 + (lane & 7)) * (PITCH * 2)
                                      + ((lane >> 3) & 1) * 16);

    // prologue: stages 0,1 <- chunks 0,1
#pragma unroll
    for (int i = 0; i < 4; ++i) {
        cpa16(sb + doff[i], Asrc[i]);
        cpa16(sb + TILE_B + doff[i], Bsrc[i]);
    }
    CPA_COMMIT();
#pragma unroll
    for (int i = 0; i < 4; ++i) {
        cpa16(sb + STAGE_B + doff[i], Asrc[i] + BK);
        cpa16(sb + STAGE_B + TILE_B + doff[i], Bsrc[i] + BK);
    }
    CPA_COMMIT();

    int stage = 0;
#pragma unroll 1
    for (int c = 0; c < NC; ++c) {
        if (c + 2 < NC) CPA_WAIT1(); else CPA_WAIT0();
        __syncthreads();

        if (c + 2 < NC) {
            int s2 = stage + 2; if (s2 >= NSTAGE) s2 -= NSTAGE;
            const uint32_t base = sb + s2 * STAGE_B;
            const int koff = (c + 2) * BK;
#pragma unroll
            for (int i = 0; i < 4; ++i) {
                cpa16(base + doff[i], Asrc[i] + koff);
                cpa16(base + TILE_B + doff[i], Bsrc[i] + koff);
            }
            CPA_COMMIT();
        }

        const uint32_t As = sb + stage * STAGE_B;
        const uint32_t Bs = As + TILE_B;
#pragma unroll
        for (int ks = 0; ks < 4; ++ks) {
            uint32_t a[4][4];
#pragma unroll
            for (int mt = 0; mt < 4; ++mt)
                ldm4(a[mt], As + lmoff + mt * 16 * (PITCH * 2) + ks * 32);
            uint32_t b[4][2];
#pragma unroll
            for (int ntp = 0; ntp < 2; ++ntp) {
                uint32_t r[4];
                ldm4(r, Bs + lbofr + ntp * 16 * (PITCH * 2) + ks * 32);
                b[2 * ntp][0] = r[0]; b[2 * ntp][1] = r[1];
                b[2 * ntp + 1][0] = r[2]; b[2 * ntp + 1][1] = r[3];
            }
#pragma unroll
            for (int mt = 0; mt < 4; ++mt)
#pragma unroll
                for (int nt = 0; nt < 4; ++nt)
                    mma16816(acc[mt][nt], a[mt], b[nt]);
        }
        if (++stage >= NSTAGE) stage = 0;
    }

    // ---------------- epilogue ----------------
    if (MODE == 1) {
        constexpr int XP = 65;
        float* xg = (float*)smem;
        __syncthreads();
        if (wn < 2) {
#pragma unroll
            for (int mt = 0; mt < 4; ++mt) {
                const int r0 = wm * 64 + mt * 16 + (lane >> 2);
#pragma unroll
                for (int nt = 0; nt < 4; ++nt) {
                    const int c0 = wn * 32 + nt * 8 + (lane & 3) * 2;
                    xg[r0 * XP + c0]           = acc[mt][nt][0];
                    xg[r0 * XP + c0 + 1]       = acc[mt][nt][1];
                    xg[(r0 + 8) * XP + c0]     = acc[mt][nt][2];
                    xg[(r0 + 8) * XP + c0 + 1] = acc[mt][nt][3];
                }
            }
        }
        __syncthreads();
        if (wn >= 2) {
#pragma unroll
            for (int mt = 0; mt < 4; ++mt) {
                const int rl = wm * 64 + mt * 16 + (lane >> 2);
                const int grow0 = tile_m * BM + rl;
#pragma unroll
                for (int nt = 0; nt < 4; ++nt) {
                    const int c0 = (wn - 2) * 32 + nt * 8 + (lane & 3) * 2;
                    float g0 = xg[rl * XP + c0];
                    float g1 = xg[rl * XP + c0 + 1];
                    float g2 = xg[(rl + 8) * XP + c0];
                    float g3 = xg[(rl + 8) * XP + c0 + 1];
                    float o0 = acc[mt][nt][0] * g0 / (1.0f + expf(-g0));
                    float o1 = acc[mt][nt][1] * g1 / (1.0f + expf(-g1));
                    float o2 = acc[mt][nt][2] * g2 / (1.0f + expf(-g2));
                    float o3 = acc[mt][nt][3] * g3 / (1.0f + expf(-g3));
                    *(uint32_t*)(g_act + (size_t)grow0 * F_DIM + tile_n * 64 + c0)       = pack_h2(o0, o1);
                    *(uint32_t*)(g_act + (size_t)(grow0 + 8) * F_DIM + tile_n * 64 + c0) = pack_h2(o2, o3);
                }
            }
        }
    } else {
#pragma unroll
        for (int mt = 0; mt < 4; ++mt) {
            const int r0 = tile_m * BM + wm * 64 + mt * 16 + (lane >> 2);
            const int t0 = g_tok[r0];
            const int t1 = g_tok[r0 + 8];
            const float w0 = g_wt[r0];
            const float w1 = g_wt[r0 + 8];
#pragma unroll
            for (int nt = 0; nt < 4; ++nt) {
                const int c0 = tile_n * BM + wn * 32 + nt * 8 + (lane & 3) * 2;
                if (t0 >= 0) {
                    atomicAdd(out + (size_t)t0 * H_DIM + c0,     w0 * acc[mt][nt][0]);
                    atomicAdd(out + (size_t)t0 * H_DIM + c0 + 1, w0 * acc[mt][nt][1]);
                }
                if (t1 >= 0) {
                    atomicAdd(out + (size_t)t1 * H_DIM + c0,     w1 * acc[mt][nt][2]);
                    atomicAdd(out + (size_t)t1 * H_DIM + c0 + 1, w1 * acc[mt][nt][3]);
                }
            }
        }
    }
}

// ---------------- launch ----------------
extern "C" void kernel_launch(void* const* d_in, const int* in_sizes, int n_in,
                              void* d_out, int out_size) {
    const float* X   = (const float*)d_in[0];
    const float* rw  = (const float*)d_in[1];
    const int*   sel = (const int*)  d_in[2];
    const float* W1  = (const float*)d_in[3];
    const float* W2  = (const float*)d_in[4];
    float* out = (float*)d_out;

    constexpr int SMEM = NSTAGE * STAGE_B;     // 110592 bytes
    static int cfg = 0;
    static __half* w1h = nullptr;
    static __half* w2h = nullptr;
    static cudaStream_t sAux;
    static cudaEvent_t evFork, evW1b, evW2;
    if (!cfg) {
        cudaFuncSetAttribute(k_gemm<1>, cudaFuncAttributeMaxDynamicSharedMemorySize, SMEM);
        cudaFuncSetAttribute(k_gemm<2>, cudaFuncAttributeMaxDynamicSharedMemorySize, SMEM);
        cudaGetSymbolAddress((void**)&w1h, g_W1h);
        cudaGetSymbolAddress((void**)&w2h, g_W2h);
        cudaStreamCreate(&sAux);
        cudaEventCreateWithFlags(&evFork, cudaEventDisableTiming);
        cudaEventCreateWithFlags(&evW1b,  cudaEventDisableTiming);
        cudaEventCreateWithFlags(&evW2,   cudaEventDisableTiming);
        cfg = 1;
    }

    const size_t W1_ELEMS = (size_t)E_NUM * F2 * H_DIM;     // 8*11264*2048
    const size_t W1_HALF  = W1_ELEMS / 2;                   // experts 0-3
    const size_t W2_ELEMS = (size_t)E_NUM * H_DIM * F_DIM;

    // stream 0: routing + gather + cvt W1[experts 0-3]
    k_init<<<256, 256>>>(out);
    k_count<<<(T_TOK * K_TOP + 255) / 256, 256>>>(sel);
    k_scan<<<1, 1>>>();
    k_scatter<<<(T_TOK * K_TOP + 255) / 256, 256>>>(sel, rw);
    k_gather<<<MAXROWS, 256>>>(X);
    k_cvt<<<2048, 256>>>(W1, w1h, W1_HALF / 4);

    // fork: aux stream converts W1[4-7] then W2, overlapping GEMM1(0-3)
    cudaEventRecord(evFork, 0);
    cudaStreamWaitEvent(sAux, evFork, 0);
    k_cvt<<<2048, 256, 0, sAux>>>(W1 + W1_HALF, w1h + W1_HALF, W1_HALF / 4);
    cudaEventRecord(evW1b, sAux);
    k_cvt<<<2048, 256, 0, sAux>>>(W2, w2h, W2_ELEMS / 4);
    cudaEventRecord(evW2, sAux);

    dim3 g1(F_DIM / 64, MAXTILES);   // 88 x 40
    k_gemm<1><<<g1, 256, SMEM>>>(w1h, nullptr, 0, 4);       // experts 0-3
    cudaStreamWaitEvent(0, evW1b, 0);
    k_gemm<1><<<g1, 256, SMEM>>>(w1h, nullptr, 4, 8);       // experts 4-7

    cudaStreamWaitEvent(0, evW2, 0);
    dim3 g2(H_DIM / BM, MAXTILES);   // 16 x 40
    k_gemm<2><<<g2, 256, SMEM>>>(w2h, out, 0, 8);
}